// round 1
// baseline (speedup 1.0000x reference)
#include <cuda_runtime.h>

// DiscreteHawkes: T=8192, S=1024, B=8192
// out[i] = relu( mu[s_i] + beta * sum_sp D[t_i, sp] * alpha[sp, s_i] )
// where D[t,sp] = sum_{tp<t} obs[tp,sp] * exp(-beta)^(t-tp)
//
// Phase 1: transpose alpha -> alphaT[s, sp]   (coalesced dot products later)
// Phase 2: decayed prefix scan of obs along T, chunked with warm-up halo
//          (a^256 ~ 7.5e-12 with beta >= 0.1 => halo of 256 is exact to fp32)
// Phase 3: warp-per-query gather dot product

#define T_DIM 8192
#define S_DIM 1024
#define B_DIM 8192
#define CHUNK 512
#define WARM  256
#define COLS_PER_BLOCK 128

// Scratch (allocation-free rule: __device__ globals)
__device__ float g_D[T_DIM * S_DIM];        // 32 MB: D[t, sp]
__device__ float g_alphaT[S_DIM * S_DIM];   // 4 MB: alphaT[s, sp] = alpha[sp, s]

// ---------------------------------------------------------------------------
// Phase 1: tiled transpose of alpha [S,S]
// ---------------------------------------------------------------------------
__global__ __launch_bounds__(256) void transpose_kernel(const float* __restrict__ alpha) {
    __shared__ float tile[32][33];
    const int tx = threadIdx.x;           // 0..31
    const int ty = threadIdx.y;           // 0..7
    const int x = blockIdx.x * 32 + tx;   // source col (s)
    const int y = blockIdx.y * 32;        // source row base (sp)
#pragma unroll
    for (int j = 0; j < 32; j += 8)
        tile[ty + j][tx] = alpha[(y + ty + j) * S_DIM + x];
    __syncthreads();
    const int ox = blockIdx.y * 32 + tx;  // dest col (sp)
    const int oy = blockIdx.x * 32;       // dest row base (s)
#pragma unroll
    for (int j = 0; j < 32; j += 8)
        g_alphaT[(oy + ty + j) * S_DIM + ox] = tile[tx][ty + j];
}

// ---------------------------------------------------------------------------
// Phase 2: chunked decayed scan along T. Each thread owns one column sp.
// Chunk c computes D[t] for t in [c*CHUNK, (c+1)*CHUNK), warming up from
// t0 = max(0, c*CHUNK - WARM) with state 0. Contributions older than WARM
// steps carry weight <= a^WARM <= e^{-25.6} ~ 7.5e-12 (beta >= 0.1): below
// fp32 rounding of the exact computation.
// ---------------------------------------------------------------------------
__global__ __launch_bounds__(COLS_PER_BLOCK) void scan_kernel(
    const int* __restrict__ obs, const float* __restrict__ beta) {
    const int sp   = blockIdx.y * COLS_PER_BLOCK + threadIdx.x;
    const int tbeg = blockIdx.x * CHUNK;
    const int t0   = (tbeg >= WARM) ? (tbeg - WARM) : 0;
    const float a  = expf(-beta[0]);

    const int* __restrict__ col = obs + sp;
    float* __restrict__ dcol = g_D + sp;

    float d = 0.0f;
    // warm-up (no stores)
#pragma unroll 8
    for (int t = t0; t < tbeg; ++t)
        d = a * (d + (float)col[t * S_DIM]);
    // main chunk: store D[t], then advance with obs[t]
#pragma unroll 8
    for (int t = tbeg; t < tbeg + CHUNK; ++t) {
        dcol[t * S_DIM] = d;
        d = a * (d + (float)col[t * S_DIM]);
    }
}

// ---------------------------------------------------------------------------
// Phase 3: warp per query. dot(D[t_i,:], alphaT[s_i,:]) over 1024 floats
// = 256 float4 -> 8 float4 per lane. Then warp shuffle reduce.
// ---------------------------------------------------------------------------
__global__ __launch_bounds__(256) void query_kernel(
    const int* __restrict__ tq, const int* __restrict__ sq,
    const float* __restrict__ beta, const float* __restrict__ mu,
    float* __restrict__ out) {
    const int q    = blockIdx.x * 8 + threadIdx.y;
    const int lane = threadIdx.x;
    const int ti = tq[q];
    const int si = sq[q];

    const float4* __restrict__ drow =
        reinterpret_cast<const float4*>(g_D + (size_t)ti * S_DIM);
    const float4* __restrict__ arow =
        reinterpret_cast<const float4*>(g_alphaT + (size_t)si * S_DIM);

    float acc = 0.0f;
#pragma unroll
    for (int j = 0; j < 8; ++j) {
        const float4 dv = drow[j * 32 + lane];
        const float4 av = arow[j * 32 + lane];
        acc += dv.x * av.x + dv.y * av.y + dv.z * av.z + dv.w * av.w;
    }
#pragma unroll
    for (int o = 16; o; o >>= 1)
        acc += __shfl_down_sync(0xffffffffu, acc, o);

    if (lane == 0)
        out[q] = fmaxf(fmaf(beta[0], acc, mu[si]), 0.0f);
}

// ---------------------------------------------------------------------------
extern "C" void kernel_launch(void* const* d_in, const int* in_sizes, int n_in,
                              void* d_out, int out_size) {
    const int*   t     = (const int*)d_in[0];
    const int*   s     = (const int*)d_in[1];
    const int*   obs   = (const int*)d_in[2];
    const float* alpha = (const float*)d_in[3];
    const float* beta  = (const float*)d_in[4];
    const float* mu    = (const float*)d_in[5];
    float* out = (float*)d_out;
    (void)in_sizes; (void)n_in; (void)out_size;

    transpose_kernel<<<dim3(S_DIM / 32, S_DIM / 32), dim3(32, 8)>>>(alpha);
    scan_kernel<<<dim3(T_DIM / CHUNK, S_DIM / COLS_PER_BLOCK),
                  COLS_PER_BLOCK>>>(obs, beta);
    query_kernel<<<B_DIM / 8, dim3(32, 8)>>>(t, s, beta, mu, out);
}

// round 2
// speedup vs baseline: 2.1441x; 2.1441x over previous
#include <cuda_runtime.h>

// DiscreteHawkes: T=8192, S=1024, B=8192
// out[i] = relu( mu[s_i] + beta * sum_sp D[t_i, sp] * alpha[sp, s_i] )
// where D[t,sp] = sum_{tp<t} obs[tp,sp] * exp(-beta)^(t-tp)
//
// Kernel 1 (fused): alpha transpose blocks + chunked decayed-scan blocks.
//   Scan: 64 chunks of 128 steps, warm-up halo of 160 steps
//   (a^160 <= e^-16 ~ 1.1e-7 for beta >= 0.1 -> below fp32 noise).
// Kernel 2: warp-per-query gather dot.

#define T_DIM 8192
#define S_DIM 1024
#define B_DIM 8192
#define CHUNK 128
#define WARM  160
#define NCHUNK (T_DIM / CHUNK)          // 64
#define NTRANS_BLK 1024                 // 32x32 tiles over 1024x1024
#define NSCAN_BLK (NCHUNK * 4)          // 4 blocks of 256 thr per chunk

// Scratch (allocation-free rule: __device__ globals)
__device__ float g_D[T_DIM * S_DIM];        // 32 MB: D[t, sp]
__device__ float g_alphaT[S_DIM * S_DIM];   // 4 MB: alphaT[s, sp] = alpha[sp, s]

// ---------------------------------------------------------------------------
// Fused kernel: blocks [0, NTRANS_BLK) transpose alpha; the rest scan obs.
// ---------------------------------------------------------------------------
__global__ __launch_bounds__(256) void prep_kernel(
    const float* __restrict__ alpha,
    const int* __restrict__ obs,
    const float* __restrict__ beta) {
    if (blockIdx.x < NTRANS_BLK) {
        // ---- transpose: 32x32 tile ----
        __shared__ float tile[32][33];
        const int bx = blockIdx.x & 31;
        const int by = blockIdx.x >> 5;
        const int tx = threadIdx.x & 31;
        const int ty = threadIdx.x >> 5;          // 0..7
        const int x = bx * 32 + tx;               // source col (s)
        const int y = by * 32;                    // source row base (sp)
#pragma unroll
        for (int j = 0; j < 32; j += 8)
            tile[ty + j][tx] = alpha[(y + ty + j) * S_DIM + x];
        __syncthreads();
        const int ox = by * 32 + tx;              // dest col (sp)
        const int oy = bx * 32;                   // dest row base (s)
#pragma unroll
        for (int j = 0; j < 32; j += 8)
            g_alphaT[(oy + ty + j) * S_DIM + ox] = tile[tx][ty + j];
    } else {
        // ---- scan: one chunk-quarter per block, one column per thread ----
        const int b     = blockIdx.x - NTRANS_BLK;
        const int chunk = b >> 2;
        const int sp    = (b & 3) * 256 + threadIdx.x;
        const int tbeg  = chunk * CHUNK;
        const int t0    = (tbeg >= WARM) ? (tbeg - WARM) : 0;
        const float a   = expf(-beta[0]);

        const int* __restrict__ col = obs + sp;
        float* __restrict__ dcol = g_D + sp;

        float d = 0.0f;
#pragma unroll 16
        for (int t = t0; t < tbeg; ++t)
            d = a * (d + (float)col[t * S_DIM]);
#pragma unroll 16
        for (int t = tbeg; t < tbeg + CHUNK; ++t) {
            dcol[t * S_DIM] = d;
            d = a * (d + (float)col[t * S_DIM]);
        }
    }
}

// ---------------------------------------------------------------------------
// Query: warp per query. dot(D[t_i,:], alphaT[s_i,:]) over 1024 floats
// = 8 float4 per lane, then warp shuffle reduce.
// ---------------------------------------------------------------------------
__global__ __launch_bounds__(256) void query_kernel(
    const int* __restrict__ tq, const int* __restrict__ sq,
    const float* __restrict__ beta, const float* __restrict__ mu,
    float* __restrict__ out) {
    const int q    = blockIdx.x * 8 + threadIdx.y;
    const int lane = threadIdx.x;
    const int ti = tq[q];
    const int si = sq[q];

    const float4* __restrict__ drow =
        reinterpret_cast<const float4*>(g_D + (size_t)ti * S_DIM);
    const float4* __restrict__ arow =
        reinterpret_cast<const float4*>(g_alphaT + (size_t)si * S_DIM);

    float acc = 0.0f;
#pragma unroll
    for (int j = 0; j < 8; ++j) {
        const float4 dv = drow[j * 32 + lane];
        const float4 av = arow[j * 32 + lane];
        acc += dv.x * av.x + dv.y * av.y + dv.z * av.z + dv.w * av.w;
    }
#pragma unroll
    for (int o = 16; o; o >>= 1)
        acc += __shfl_down_sync(0xffffffffu, acc, o);

    if (lane == 0)
        out[q] = fmaxf(fmaf(beta[0], acc, mu[si]), 0.0f);
}

// ---------------------------------------------------------------------------
extern "C" void kernel_launch(void* const* d_in, const int* in_sizes, int n_in,
                              void* d_out, int out_size) {
    const int*   t     = (const int*)d_in[0];
    const int*   s     = (const int*)d_in[1];
    const int*   obs   = (const int*)d_in[2];
    const float* alpha = (const float*)d_in[3];
    const float* beta  = (const float*)d_in[4];
    const float* mu    = (const float*)d_in[5];
    float* out = (float*)d_out;
    (void)in_sizes; (void)n_in; (void)out_size;

    prep_kernel<<<NTRANS_BLK + NSCAN_BLK, 256>>>(alpha, obs, beta);
    query_kernel<<<B_DIM / 8, dim3(32, 8)>>>(t, s, beta, mu, out);
}

// round 3
// speedup vs baseline: 2.3380x; 1.0904x over previous
#include <cuda_runtime.h>
#include <cuda_fp16.h>

// DiscreteHawkes: T=8192, S=1024, B=8192
// out[i] = relu( mu[s_i] + beta * sum_sp D[t_i, sp] * alpha[sp, s_i] )
// where D[t,sp] = sum_{tp<t} obs[tp,sp] * exp(-beta)^(t-tp)
//
// Kernel 1 (fused): chunked decayed-scan blocks (fp16 D out) + alpha transpose.
//   Scan: 64 chunks of 128 steps, warm-up halo of 128 steps
//   (a^128 <= e^-12.8 ~ 2.8e-6 for beta >= 0.1 -> below fp16 D noise).
// Kernel 2: 2 queries per warp, gather dot over fp16 D row x fp32 alphaT row.

#define T_DIM 8192
#define S_DIM 1024
#define B_DIM 8192
#define CHUNK 128
#define WARM  128
#define NCHUNK (T_DIM / CHUNK)          // 64
#define NSCAN_BLK (NCHUNK * 2)          // 2 blocks (512 cols each) per chunk
#define NTRANS_BLK 1024                 // 32x32 tiles over 1024x1024

// Scratch (allocation-free rule: __device__ globals)
__device__ __half g_Dh[T_DIM * S_DIM];      // 16 MB: D[t, sp] fp16
__device__ float  g_alphaT[S_DIM * S_DIM];  // 4 MB: alphaT[s, sp] = alpha[sp, s]

// ---------------------------------------------------------------------------
// Fused kernel: blocks [0, NSCAN_BLK) scan obs; the rest transpose alpha.
// ---------------------------------------------------------------------------
__global__ __launch_bounds__(256) void prep_kernel(
    const float* __restrict__ alpha,
    const int* __restrict__ obs,
    const float* __restrict__ beta) {
    if (blockIdx.x < NSCAN_BLK) {
        // ---- scan: each thread owns 2 adjacent columns ----
        const int b     = blockIdx.x;
        const int chunk = b >> 1;
        const int c0    = (b & 1) * 512 + threadIdx.x * 2;
        const int tbeg  = chunk * CHUNK;
        const int t0    = (tbeg >= WARM) ? (tbeg - WARM) : 0;
        const float a   = expf(-beta[0]);

        const int2* __restrict__ col =
            reinterpret_cast<const int2*>(obs + c0);
        __half2* __restrict__ dcol =
            reinterpret_cast<__half2*>(g_Dh + c0);

        float d0 = 0.0f, d1 = 0.0f;
#pragma unroll 16
        for (int t = t0; t < tbeg; ++t) {
            const int2 x = col[t * (S_DIM / 2)];
            d0 = fmaf(a, d0, a * (float)x.x);
            d1 = fmaf(a, d1, a * (float)x.y);
        }
#pragma unroll 16
        for (int t = tbeg; t < tbeg + CHUNK; ++t) {
            dcol[t * (S_DIM / 2)] = __floats2half2_rn(d0, d1);
            const int2 x = col[t * (S_DIM / 2)];
            d0 = fmaf(a, d0, a * (float)x.x);
            d1 = fmaf(a, d1, a * (float)x.y);
        }
    } else {
        // ---- transpose: 32x32 tile ----
        __shared__ float tile[32][33];
        const int bi = blockIdx.x - NSCAN_BLK;
        const int bx = bi & 31;
        const int by = bi >> 5;
        const int tx = threadIdx.x & 31;
        const int ty = threadIdx.x >> 5;          // 0..7
        const int x = bx * 32 + tx;               // source col (s)
        const int y = by * 32;                    // source row base (sp)
#pragma unroll
        for (int j = 0; j < 32; j += 8)
            tile[ty + j][tx] = alpha[(y + ty + j) * S_DIM + x];
        __syncthreads();
        const int ox = by * 32 + tx;              // dest col (sp)
        const int oy = bx * 32;                   // dest row base (s)
#pragma unroll
        for (int j = 0; j < 32; j += 8)
            g_alphaT[(oy + ty + j) * S_DIM + ox] = tile[tx][ty + j];
    }
}

// ---------------------------------------------------------------------------
// Query: 2 queries per warp (interleaved for MLP).
// Per lane per query: 8x LDG.64 (fp16 D) + 8x LDG.128 (fp32 alphaT).
// ---------------------------------------------------------------------------
__global__ __launch_bounds__(256) void query_kernel(
    const int* __restrict__ tq, const int* __restrict__ sq,
    const float* __restrict__ beta, const float* __restrict__ mu,
    float* __restrict__ out) {
    const int warp = blockIdx.x * 8 + (threadIdx.x >> 5);
    const int lane = threadIdx.x & 31;
    const int q0 = warp * 2;
    const int q1 = q0 + 1;

    const int t0 = tq[q0], s0 = sq[q0];
    const int t1 = tq[q1], s1 = sq[q1];

    const uint2* __restrict__ d0 =
        reinterpret_cast<const uint2*>(g_Dh + (size_t)t0 * S_DIM);
    const uint2* __restrict__ d1 =
        reinterpret_cast<const uint2*>(g_Dh + (size_t)t1 * S_DIM);
    const float4* __restrict__ a0 =
        reinterpret_cast<const float4*>(g_alphaT + (size_t)s0 * S_DIM);
    const float4* __restrict__ a1 =
        reinterpret_cast<const float4*>(g_alphaT + (size_t)s1 * S_DIM);

    float acc0 = 0.0f, acc1 = 0.0f;
#pragma unroll
    for (int k = 0; k < 8; ++k) {
        const int idx = k * 32 + lane;
        const uint2  dv0 = d0[idx];
        const float4 av0 = a0[idx];
        const uint2  dv1 = d1[idx];
        const float4 av1 = a1[idx];

        const float2 f00 = __half22float2(*reinterpret_cast<const __half2*>(&dv0.x));
        const float2 f01 = __half22float2(*reinterpret_cast<const __half2*>(&dv0.y));
        acc0 += f00.x * av0.x + f00.y * av0.y + f01.x * av0.z + f01.y * av0.w;

        const float2 f10 = __half22float2(*reinterpret_cast<const __half2*>(&dv1.x));
        const float2 f11 = __half22float2(*reinterpret_cast<const __half2*>(&dv1.y));
        acc1 += f10.x * av1.x + f10.y * av1.y + f11.x * av1.z + f11.y * av1.w;
    }
#pragma unroll
    for (int o = 16; o; o >>= 1) {
        acc0 += __shfl_down_sync(0xffffffffu, acc0, o);
        acc1 += __shfl_down_sync(0xffffffffu, acc1, o);
    }

    if (lane == 0) {
        const float bt = beta[0];
        out[q0] = fmaxf(fmaf(bt, acc0, mu[s0]), 0.0f);
        out[q1] = fmaxf(fmaf(bt, acc1, mu[s1]), 0.0f);
    }
}

// ---------------------------------------------------------------------------
extern "C" void kernel_launch(void* const* d_in, const int* in_sizes, int n_in,
                              void* d_out, int out_size) {
    const int*   t     = (const int*)d_in[0];
    const int*   s     = (const int*)d_in[1];
    const int*   obs   = (const int*)d_in[2];
    const float* alpha = (const float*)d_in[3];
    const float* beta  = (const float*)d_in[4];
    const float* mu    = (const float*)d_in[5];
    float* out = (float*)d_out;
    (void)in_sizes; (void)n_in; (void)out_size;

    prep_kernel<<<NSCAN_BLK + NTRANS_BLK, 256>>>(alpha, obs, beta);
    query_kernel<<<B_DIM / 16, 256>>>(t, s, beta, mu, out);
}

// round 4
// speedup vs baseline: 2.8063x; 1.2003x over previous
#include <cuda_runtime.h>
#include <cuda_fp16.h>

// DiscreteHawkes: T=8192, S=1024, B=8192
// out[i] = relu( mu[s_i] + beta * sum_sp D[t_i, sp] * alpha[sp, s_i] )
// where D[t,sp] = sum_{tp<t} obs[tp,sp] * exp(-beta)^(t-tp)
//
// Kernel 1 (fused):
//   - scan blocks: chunked decayed scan along T (fp16 D out), 1 col/thread,
//     CHUNK=128 with WARM=128 halo (a^128 <= e^-12.8 ~ 2.8e-6 for beta>=0.1).
//   - transpose blocks: alpha -> alphaT packed fp16.
// Kernel 2: 1 query per warp; fp16 D row x fp16 alphaT row, fp32 accumulate.

#define T_DIM 8192
#define S_DIM 1024
#define B_DIM 8192
#define CHUNK 128
#define WARM  128
#define NCHUNK (T_DIM / CHUNK)            // 64
#define NSCAN_BLK (NCHUNK * 4)            // 4 col-blocks (256 cols) per chunk -> 256
#define NTRANS_BLK 512                    // 64sp x 32s tiles over 1024x1024

// Scratch (allocation-free rule: __device__ globals)
__device__ __half g_Dh[T_DIM * S_DIM];        // 16 MB: D[t, sp] fp16
__device__ __half g_alphaTh[S_DIM * S_DIM];   // 2 MB: alphaT[s, sp] fp16

// ---------------------------------------------------------------------------
// Fused prep: blocks [0, NSCAN_BLK) scan obs; the rest transpose alpha->fp16.
// ---------------------------------------------------------------------------
__global__ __launch_bounds__(256) void prep_kernel(
    const float* __restrict__ alpha,
    const int* __restrict__ obs,
    const float* __restrict__ beta) {
    if (blockIdx.x < NSCAN_BLK) {
        // ---- scan: one column per thread ----
        const int b     = blockIdx.x;
        const int chunk = b >> 2;
        const int c     = (b & 3) * 256 + threadIdx.x;
        const int tbeg  = chunk * CHUNK;
        const int t0    = (tbeg >= WARM) ? (tbeg - WARM) : 0;
        const float a   = expf(-beta[0]);

        const int* __restrict__ col = obs + c;
        __half* __restrict__ dcol = g_Dh + c;

        float d = 0.0f;
#pragma unroll 16
        for (int t = t0; t < tbeg; ++t)
            d = fmaf(a, d, a * (float)col[t * S_DIM]);
#pragma unroll 16
        for (int t = tbeg; t < tbeg + CHUNK; ++t) {
            dcol[t * S_DIM] = __float2half_rn(d);
            d = fmaf(a, d, a * (float)col[t * S_DIM]);
        }
    } else {
        // ---- transpose to fp16: 64(sp) x 32(s) tile ----
        __shared__ float tile[64][33];     // [sp_local][s_local]
        const int bi  = blockIdx.x - NSCAN_BLK;
        const int spb = (bi & 15) * 64;    // 16 sp-tiles
        const int sb  = (bi >> 4) * 32;    // 32 s-tiles
        const int lane = threadIdx.x & 31;
        const int wrp  = threadIdx.x >> 5; // 0..7
#pragma unroll
        for (int j = 0; j < 8; ++j) {
            const int r = wrp + j * 8;     // sp_local 0..63
            tile[r][lane] = alpha[(spb + r) * S_DIM + (sb + lane)];
        }
        __syncthreads();
        __half2* __restrict__ outh2 =
            reinterpret_cast<__half2*>(g_alphaTh);
#pragma unroll
        for (int j = 0; j < 4; ++j) {
            const int sl = wrp + j * 8;    // s_local 0..31
            const __half2 v = __floats2half2_rn(tile[2 * lane][sl],
                                                tile[2 * lane + 1][sl]);
            outh2[(sb + sl) * (S_DIM / 2) + (spb >> 1) + lane] = v;
        }
    }
}

// ---------------------------------------------------------------------------
// Query: 1 query per warp. Row dot of 1024 fp16 x fp16 -> fp32.
// Per lane: 4x uint4 (D) + 4x uint4 (alphaT), all independent.
// ---------------------------------------------------------------------------
__global__ __launch_bounds__(256) void query_kernel(
    const int* __restrict__ tq, const int* __restrict__ sq,
    const float* __restrict__ beta, const float* __restrict__ mu,
    float* __restrict__ out) {
    const int q    = blockIdx.x * 8 + (threadIdx.x >> 5);
    const int lane = threadIdx.x & 31;
    const int ti = tq[q];
    const int si = sq[q];

    const uint4* __restrict__ drow =
        reinterpret_cast<const uint4*>(g_Dh + (size_t)ti * S_DIM);
    const uint4* __restrict__ arow =
        reinterpret_cast<const uint4*>(g_alphaTh + (size_t)si * S_DIM);

    // issue all 8 loads first (max MLP)
    uint4 dv[4], av[4];
#pragma unroll
    for (int k = 0; k < 4; ++k) {
        dv[k] = drow[k * 32 + lane];
        av[k] = arow[k * 32 + lane];
    }

    float acc = 0.0f;
#pragma unroll
    for (int k = 0; k < 4; ++k) {
        const __half2* dh = reinterpret_cast<const __half2*>(&dv[k]);
        const __half2* ah = reinterpret_cast<const __half2*>(&av[k]);
#pragma unroll
        for (int j = 0; j < 4; ++j) {
            const float2 df = __half22float2(dh[j]);
            const float2 af = __half22float2(ah[j]);
            acc = fmaf(df.x, af.x, acc);
            acc = fmaf(df.y, af.y, acc);
        }
    }
#pragma unroll
    for (int o = 16; o; o >>= 1)
        acc += __shfl_down_sync(0xffffffffu, acc, o);

    if (lane == 0)
        out[q] = fmaxf(fmaf(beta[0], acc, mu[si]), 0.0f);
}

// ---------------------------------------------------------------------------
extern "C" void kernel_launch(void* const* d_in, const int* in_sizes, int n_in,
                              void* d_out, int out_size) {
    const int*   t     = (const int*)d_in[0];
    const int*   s     = (const int*)d_in[1];
    const int*   obs   = (const int*)d_in[2];
    const float* alpha = (const float*)d_in[3];
    const float* beta  = (const float*)d_in[4];
    const float* mu    = (const float*)d_in[5];
    float* out = (float*)d_out;
    (void)in_sizes; (void)n_in; (void)out_size;

    prep_kernel<<<NSCAN_BLK + NTRANS_BLK, 256>>>(alpha, obs, beta);
    query_kernel<<<B_DIM / 8, 256>>>(t, s, beta, mu, out);
}